// round 9
// baseline (speedup 1.0000x reference)
#include <cuda_runtime.h>
#include <cuda_bf16.h>
#include <cstdint>

#define B_ 2
#define H_ 16
#define S_ 2048
#define D_ 128
#define SCALE 0.08838834764831845f   // 1/sqrt(128)
#define NEG (-1e9f)

#define CW 72                        // chunk row stride (64 data + 8 pad) bf16
#define CH_ELEMS (128 * CW)          // elems per tile per stage
#define SM_BYTES (8 * CH_ELEMS * 2)  // 2 stages x 4 tiles = 147456 B
#define SGW 132                      // fp32 staging row stride (floats)

// Pre-transposed V: Vt[bh][n][k] = V[bh][k][n], split into bf16 hi/lo
__device__ __align__(16) __nv_bfloat16 g_VtHi[(size_t)32 * 128 * 2048];
__device__ __align__(16) __nv_bfloat16 g_VtLo[(size_t)32 * 128 * 2048];

// ---------------------------------------------------------------------------
__device__ __forceinline__ void mma_bf16(float* d,
                                         uint32_t a0, uint32_t a1, uint32_t a2, uint32_t a3,
                                         uint32_t b0, uint32_t b1) {
    asm volatile(
        "mma.sync.aligned.m16n8k16.row.col.f32.bf16.bf16.f32 "
        "{%0,%1,%2,%3}, {%4,%5,%6,%7}, {%8,%9}, {%0,%1,%2,%3};"
        : "+f"(d[0]), "+f"(d[1]), "+f"(d[2]), "+f"(d[3])
        : "r"(a0), "r"(a1), "r"(a2), "r"(a3), "r"(b0), "r"(b1));
}

__device__ __forceinline__ void ldm_x4(uint32_t& r0, uint32_t& r1, uint32_t& r2, uint32_t& r3,
                                       uint32_t addr) {
    asm volatile("ldmatrix.sync.aligned.m8n8.x4.shared.b16 {%0,%1,%2,%3}, [%4];"
                 : "=r"(r0), "=r"(r1), "=r"(r2), "=r"(r3) : "r"(addr));
}

__device__ __forceinline__ uint32_t smem_u32(const void* p) {
    return (uint32_t)__cvta_generic_to_shared(p);
}

__device__ __forceinline__ uint32_t pack2(__nv_bfloat16 a, __nv_bfloat16 b) {
    return (uint32_t)__bfloat16_as_ushort(a) | ((uint32_t)__bfloat16_as_ushort(b) << 16);
}

__device__ __forceinline__ void store_hilo4(__nv_bfloat16* hi, __nv_bfloat16* lo,
                                            uint32_t off, float4 v) {
    __nv_bfloat16 h0 = __float2bfloat16(v.x), h1 = __float2bfloat16(v.y);
    __nv_bfloat16 h2 = __float2bfloat16(v.z), h3 = __float2bfloat16(v.w);
    __nv_bfloat16 l0 = __float2bfloat16(v.x - __bfloat162float(h0));
    __nv_bfloat16 l1 = __float2bfloat16(v.y - __bfloat162float(h1));
    __nv_bfloat16 l2 = __float2bfloat16(v.z - __bfloat162float(h2));
    __nv_bfloat16 l3 = __float2bfloat16(v.w - __bfloat162float(h3));
    uint2 hp; hp.x = pack2(h0, h1); hp.y = pack2(h2, h3);
    uint2 lp; lp.x = pack2(l0, l1); lp.y = pack2(l2, l3);
    *(uint2*)(hi + off) = hp;
    *(uint2*)(lo + off) = lp;
}

__device__ __forceinline__ float warpRedMax(float v) {
    #pragma unroll
    for (int o = 16; o > 0; o >>= 1) v = fmaxf(v, __shfl_xor_sync(0xffffffffu, v, o));
    return v;
}
__device__ __forceinline__ float warpRedSum(float v) {
    #pragma unroll
    for (int o = 16; o > 0; o >>= 1) v += __shfl_xor_sync(0xffffffffu, v, o);
    return v;
}

// MMA over one 64-wide chunk (4 ksteps), accumulators 16x4 per thread
__device__ __forceinline__ void mma_chunk(float acc[16][4],
                                          uint32_t aHi, uint32_t aLo,
                                          uint32_t bHi, uint32_t bLo) {
    #pragma unroll
    for (int ks = 0; ks < 4; ++ks) {
        const uint32_t kb = ks * 32;   // 16 bf16 = 32 bytes
        uint32_t ah0, ah1, ah2, ah3, al0, al1, al2, al3;
        ldm_x4(ah0, ah1, ah2, ah3, aHi + kb);
        ldm_x4(al0, al1, al2, al3, aLo + kb);
        #pragma unroll
        for (int nt = 0; nt < 16; nt += 2) {
            const uint32_t bo = nt * (8 * CW * 2) + kb;
            uint32_t bh0, bh1, bh2, bh3, bl0, bl1, bl2, bl3;
            ldm_x4(bh0, bh1, bh2, bh3, bHi + bo);
            ldm_x4(bl0, bl1, bl2, bl3, bLo + bo);
            mma_bf16(acc[nt],     ah0, ah1, ah2, ah3, bh0, bh1);
            mma_bf16(acc[nt],     ah0, ah1, ah2, ah3, bl0, bl1);
            mma_bf16(acc[nt],     al0, al1, al2, al3, bh0, bh1);
            mma_bf16(acc[nt + 1], ah0, ah1, ah2, ah3, bh2, bh3);
            mma_bf16(acc[nt + 1], ah0, ah1, ah2, ah3, bl2, bl3);
            mma_bf16(acc[nt + 1], al0, al1, al2, al3, bh2, bh3);
        }
    }
}

// ---------------------------------------------------------------------------
// K0: V -> Vt (transposed) bf16 hi/lo
// ---------------------------------------------------------------------------
__global__ __launch_bounds__(256) void vt_kernel(const float* __restrict__ V) {
    __shared__ float t[32][33];
    const int k0 = blockIdx.x * 32, n0 = blockIdx.y * 32, bh = blockIdx.z;
    const int tid = threadIdx.x, c = tid & 31, r0 = tid >> 5;
    const float* Vb = V + (size_t)bh * S_ * D_;
    #pragma unroll
    for (int rr = r0; rr < 32; rr += 8)
        t[rr][c] = Vb[(size_t)(k0 + rr) * D_ + n0 + c];
    __syncthreads();
    __nv_bfloat16* Hb = g_VtHi + (size_t)bh * D_ * S_;
    __nv_bfloat16* Lb = g_VtLo + (size_t)bh * D_ * S_;
    #pragma unroll
    for (int rr = r0; rr < 32; rr += 8) {
        float x = t[c][rr];
        __nv_bfloat16 h = __float2bfloat16(x);
        __nv_bfloat16 l = __float2bfloat16(x - __bfloat162float(h));
        size_t o = (size_t)(n0 + rr) * S_ + k0 + c;
        Hb[o] = h;
        Lb[o] = l;
    }
}

// ---------------------------------------------------------------------------
// K1: scores = Q K^T * scale + mask -> attn scratch. 128x128 tile per CTA.
// Two 64-wide k-chunks, double buffered: chunk1 LDG overlaps chunk0 MMA.
// ---------------------------------------------------------------------------
__global__ __launch_bounds__(256) void scores_mma_kernel(
    const float* __restrict__ Q, const float* __restrict__ K,
    const int* __restrict__ mask, float* __restrict__ attn)
{
    const int bh = blockIdx.z, b = bh >> 4;
    const int i0 = blockIdx.y * 128, j0 = blockIdx.x * 128;
    const int tid = threadIdx.x;

    if (j0 + 128 <= (i0 * 4) / 5) return;   // fully-window tile: no work

    float* attnBase = attn + ((size_t)bh * S_ + i0) * S_ + j0;

    extern __shared__ __nv_bfloat16 sm[];
    __nv_bfloat16* stBase[2] = { sm, sm + 4 * CH_ELEMS };

    const float* Qb = Q + ((size_t)bh * S_ + i0) * D_;
    const float* Kb = K + ((size_t)bh * S_ + j0) * D_;

    const int lane = tid & 31, warp = tid >> 5;
    const int g = lane >> 2, c = lane & 3;
    const int m0 = warp * 16;

    float acc[16][4];
    #pragma unroll
    for (int nt = 0; nt < 16; ++nt)
        #pragma unroll
        for (int q = 0; q < 4; ++q) acc[nt][q] = 0.0f;

    const uint32_t aRowOff = ((m0 + (lane & 15)) * CW + (lane >> 4) * 8) * 2;
    const uint32_t bRowOff = ((((lane >> 4) << 3) + (lane & 7)) * CW + ((lane >> 3) & 1) * 8) * 2;
    uint32_t aHiA[2], aLoA[2], bHiA[2], bLoA[2];
    #pragma unroll
    for (int s = 0; s < 2; ++s) {
        uint32_t bs = smem_u32(stBase[s]);
        aHiA[s] = bs + aRowOff;
        aLoA[s] = bs + CH_ELEMS * 2 + aRowOff;
        bHiA[s] = bs + 2 * CH_ELEMS * 2 + bRowOff;
        bLoA[s] = bs + 3 * CH_ELEMS * 2 + bRowOff;
    }

    float4 qv[8], kv[8];

    // chunk 0: load + store
    #pragma unroll
    for (int it = 0; it < 8; ++it) {
        int idx = it * 256 + tid;
        int row = idx >> 4, c4 = (idx & 15) << 2;
        qv[it] = *(const float4*)&Qb[(size_t)row * D_ + c4];
        kv[it] = *(const float4*)&Kb[(size_t)row * D_ + c4];
    }
    {
        __nv_bfloat16* Ahi = stBase[0];
        __nv_bfloat16* Alo = stBase[0] + CH_ELEMS;
        __nv_bfloat16* Bhi = stBase[0] + 2 * CH_ELEMS;
        __nv_bfloat16* Blo = stBase[0] + 3 * CH_ELEMS;
        #pragma unroll
        for (int it = 0; it < 8; ++it) {
            int idx = it * 256 + tid;
            int row = idx >> 4, c4 = (idx & 15) << 2;
            store_hilo4(Ahi, Alo, row * CW + c4, qv[it]);
            store_hilo4(Bhi, Blo, row * CW + c4, kv[it]);
        }
    }
    __syncthreads();

    // prefetch chunk 1 (LDG in flight during chunk 0 MMA)
    #pragma unroll
    for (int it = 0; it < 8; ++it) {
        int idx = it * 256 + tid;
        int row = idx >> 4, c4 = (idx & 15) << 2;
        qv[it] = *(const float4*)&Qb[(size_t)row * D_ + 64 + c4];
        kv[it] = *(const float4*)&Kb[(size_t)row * D_ + 64 + c4];
    }

    mma_chunk(acc, aHiA[0], aLoA[0], bHiA[0], bLoA[0]);

    {
        __nv_bfloat16* Ahi = stBase[1];
        __nv_bfloat16* Alo = stBase[1] + CH_ELEMS;
        __nv_bfloat16* Bhi = stBase[1] + 2 * CH_ELEMS;
        __nv_bfloat16* Blo = stBase[1] + 3 * CH_ELEMS;
        #pragma unroll
        for (int it = 0; it < 8; ++it) {
            int idx = it * 256 + tid;
            int row = idx >> 4, c4 = (idx & 15) << 2;
            store_hilo4(Ahi, Alo, row * CW + c4, qv[it]);
            store_hilo4(Bhi, Blo, row * CW + c4, kv[it]);
        }
    }
    __syncthreads();

    mma_chunk(acc, aHiA[1], aLoA[1], bHiA[1], bLoA[1]);
    __syncthreads();   // all warps done reading smem; reuse as fp32 staging

    float* stg = (float*)sm;
    #pragma unroll
    for (int nt = 0; nt < 16; ++nt) {
        *(float2*)&stg[(m0 + g) * SGW + nt * 8 + 2 * c]     = make_float2(acc[nt][0], acc[nt][1]);
        *(float2*)&stg[(m0 + g + 8) * SGW + nt * 8 + 2 * c] = make_float2(acc[nt][2], acc[nt][3]);
    }
    __syncthreads();

    const int* mB = mask + (size_t)b * S_ * S_;
    #pragma unroll
    for (int it = 0; it < 16; ++it) {
        int idx = it * 256 + tid;
        int r = idx >> 5, cc = (idx & 31) * 4;
        int i = i0 + r, thr = (i * 4) / 5, j = j0 + cc;
        int4 mv = *(const int4*)&mB[(size_t)i * S_ + j];
        float4 s = *(float4*)&stg[r * SGW + cc];
        float4 v;
        v.x = (mv.x || (j + 0) < thr) ? NEG : s.x * SCALE;
        v.y = (mv.y || (j + 1) < thr) ? NEG : s.y * SCALE;
        v.z = (mv.z || (j + 2) < thr) ? NEG : s.z * SCALE;
        v.w = (mv.w || (j + 3) < thr) ? NEG : s.w * SCALE;
        *(float4*)&attnBase[(size_t)r * S_ + cc] = v;
    }
}

// ---------------------------------------------------------------------------
// K2: row softmax. Reads only [jStart, S); zero-fills [0, jStart).
// ---------------------------------------------------------------------------
__global__ __launch_bounds__(256) void softmax_kernel(float* __restrict__ attn)
{
    const int row = blockIdx.x;
    const int i = row & (S_ - 1);
    const int i0 = i & ~127;
    const int jStart = (((i0 * 4) / 5) >> 7) << 7;
    float* p = attn + (size_t)row * S_;
    const int tid = threadIdx.x;

    const int n4 = (S_ - jStart) >> 2;
    float4* p4 = (float4*)(p + jStart);
    const bool val0 = tid < n4;
    const bool val1 = tid + 256 < n4;

    float4 v0 = make_float4(NEG, NEG, NEG, NEG);
    float4 v1 = make_float4(NEG, NEG, NEG, NEG);
    if (val0) v0 = p4[tid];
    if (val1) v1 = p4[tid + 256];

    __shared__ float red[8];

    float m = fmaxf(fmaxf(fmaxf(v0.x, v0.y), fmaxf(v0.z, v0.w)),
                    fmaxf(fmaxf(v1.x, v1.y), fmaxf(v1.z, v1.w)));
    m = warpRedMax(m);
    if ((tid & 31) == 0) red[tid >> 5] = m;
    __syncthreads();
    float bm = red[0];
    #pragma unroll
    for (int k = 1; k < 8; ++k) bm = fmaxf(bm, red[k]);
    __syncthreads();

    v0.x = __expf(v0.x - bm); v0.y = __expf(v0.y - bm);
    v0.z = __expf(v0.z - bm); v0.w = __expf(v0.w - bm);
    v1.x = __expf(v1.x - bm); v1.y = __expf(v1.y - bm);
    v1.z = __expf(v1.z - bm); v1.w = __expf(v1.w - bm);

    float s = 0.0f;
    if (val0) s += (v0.x + v0.y) + (v0.z + v0.w);
    if (val1) s += (v1.x + v1.y) + (v1.z + v1.w);
    s = warpRedSum(s);
    if ((tid & 31) == 0) red[tid >> 5] = s;
    __syncthreads();
    float bs = 0.0f;
    #pragma unroll
    for (int k = 0; k < 8; ++k) bs += red[k];

    const float inv = 1.0f / bs;
    if (val0) {
        v0.x *= inv; v0.y *= inv; v0.z *= inv; v0.w *= inv;
        p4[tid] = v0;
    }
    if (val1) {
        v1.x *= inv; v1.y *= inv; v1.z *= inv; v1.w *= inv;
        p4[tid + 256] = v1;
    }

    const float4 z = make_float4(0.f, 0.f, 0.f, 0.f);
    const int nz4 = jStart >> 2;
    for (int idx = tid; idx < nz4; idx += 256)
        ((float4*)p)[idx] = z;
}

// ---------------------------------------------------------------------------
// K3: context = attn @ V. 128x128 output per CTA.
// Software pipeline over 64-wide k-chunks: LDG(next) -> MMA(cur) -> STS(next).
// ---------------------------------------------------------------------------
__global__ __launch_bounds__(256) void context_mma_kernel(
    const float* __restrict__ attn, float* __restrict__ ctx)
{
    const int i0 = blockIdx.x * 128, bh = blockIdx.y;
    const int tid = threadIdx.x;

    extern __shared__ __nv_bfloat16 sm[];
    __nv_bfloat16* stBase[2] = { sm, sm + 4 * CH_ELEMS };

    const float* Pb = attn + ((size_t)bh * S_ + i0) * S_;
    const __nv_bfloat16* VtH = g_VtHi + (size_t)bh * D_ * S_;
    const __nv_bfloat16* VtL = g_VtLo + (size_t)bh * D_ * S_;

    const int lane = tid & 31, warp = tid >> 5;
    const int g = lane >> 2, c = lane & 3;
    const int m0 = warp * 16;

    float acc[16][4];
    #pragma unroll
    for (int nt = 0; nt < 16; ++nt)
        #pragma unroll
        for (int q = 0; q < 4; ++q) acc[nt][q] = 0.0f;

    const uint32_t aRowOff = ((m0 + (lane & 15)) * CW + (lane >> 4) * 8) * 2;
    const uint32_t bRowOff = ((((lane >> 4) << 3) + (lane & 7)) * CW + ((lane >> 3) & 1) * 8) * 2;
    uint32_t aHiA[2], aLoA[2], bHiA[2], bLoA[2];
    #pragma unroll
    for (int s = 0; s < 2; ++s) {
        uint32_t bs = smem_u32(stBase[s]);
        aHiA[s] = bs + aRowOff;
        aLoA[s] = bs + CH_ELEMS * 2 + aRowOff;
        bHiA[s] = bs + 2 * CH_ELEMS * 2 + bRowOff;
        bLoA[s] = bs + 3 * CH_ELEMS * 2 + bRowOff;
    }

    const int ch0 = (((i0 * 4) / 5) >> 7) * 2;   // first nonzero 64-chunk
    const int chLast = 31;

    float4 pv[8];
    uint4 vh[4], vl[4];

    // prefetch + store chunk ch0
    {
        const int k0g = ch0 * 64;
        #pragma unroll
        for (int it = 0; it < 8; ++it) {
            int idx = it * 256 + tid;
            int row = idx >> 4, c4 = (idx & 15) << 2;
            pv[it] = *(const float4*)&Pb[(size_t)row * S_ + k0g + c4];
        }
        #pragma unroll
        for (int it = 0; it < 4; ++it) {
            int idx = it * 256 + tid;
            int n = idx >> 3, k8 = (idx & 7) << 3;
            vh[it] = *(const uint4*)&VtH[(size_t)n * S_ + k0g + k8];
            vl[it] = *(const uint4*)&VtL[(size_t)n * S_ + k0g + k8];
        }
        __nv_bfloat16* base = stBase[ch0 & 1];
        __nv_bfloat16* Phi = base, *Plo = base + CH_ELEMS;
        __nv_bfloat16* Vhi = base + 2 * CH_ELEMS, *Vlo = base + 3 * CH_ELEMS;
        #pragma unroll
        for (int it = 0; it < 8; ++it) {
            int idx = it * 256 + tid;
            int row = idx >> 4, c4 = (idx & 15) << 2;
            store_hilo4(Phi, Plo, row * CW + c4, pv[it]);
        }
        #pragma unroll
        for (int it = 0; it < 4; ++it) {
            int idx = it * 256 + tid;
            int n = idx >> 3, k8 = (idx & 7) << 3;
            *(uint4*)(Vhi + n * CW + k8) = vh[it];
            *(uint4*)(Vlo + n * CW + k8) = vl[it];
        }
    }
    __syncthreads();

    for (int ch = ch0; ch <= chLast; ++ch) {
        const int nxt = ch + 1;
        if (nxt <= chLast) {
            const int k0g = nxt * 64;
            #pragma unroll
            for (int it = 0; it < 8; ++it) {
                int idx = it * 256 + tid;
                int row = idx >> 4, c4 = (idx & 15) << 2;
                pv[it] = *(const float4*)&Pb[(size_t)row * S_ + k0g + c4];
            }
            #pragma unroll
            for (int it = 0; it < 4; ++it) {
                int idx = it * 256 + tid;
                int n = idx >> 3, k8 = (idx & 7) << 3;
                vh[it] = *(const uint4*)&VtH[(size_t)n * S_ + k0g + k8];
                vl[it] = *(const uint4*)&VtL[(size_t)n * S_ + k0g + k8];
            }
        }

        mma_chunk(acc, aHiA[ch & 1], aLoA[ch & 1], bHiA[ch & 1], bLoA[ch & 1]);

        if (nxt <= chLast) {
            __nv_bfloat16* base = stBase[nxt & 1];
            __nv_bfloat16* Phi = base, *Plo = base + CH_ELEMS;
            __nv_bfloat16* Vhi = base + 2 * CH_ELEMS, *Vlo = base + 3 * CH_ELEMS;
            #pragma unroll
            for (int it = 0; it < 8; ++it) {
                int idx = it * 256 + tid;
                int row = idx >> 4, c4 = (idx & 15) << 2;
                store_hilo4(Phi, Plo, row * CW + c4, pv[it]);
            }
            #pragma unroll
            for (int it = 0; it < 4; ++it) {
                int idx = it * 256 + tid;
                int n = idx >> 3, k8 = (idx & 7) << 3;
                *(uint4*)(Vhi + n * CW + k8) = vh[it];
                *(uint4*)(Vlo + n * CW + k8) = vl[it];
            }
            __syncthreads();
        }
    }
    __syncthreads();   // all warps done with smem; reuse as staging

    float* stg = (float*)sm;
    #pragma unroll
    for (int nt = 0; nt < 16; ++nt) {
        *(float2*)&stg[(m0 + g) * SGW + nt * 8 + 2 * c]     = make_float2(acc[nt][0], acc[nt][1]);
        *(float2*)&stg[(m0 + g + 8) * SGW + nt * 8 + 2 * c] = make_float2(acc[nt][2], acc[nt][3]);
    }
    __syncthreads();

    #pragma unroll
    for (int it = 0; it < 16; ++it) {
        int idx = it * 256 + tid;
        int r = idx >> 5, c4 = (idx & 31) << 2;
        *(float4*)&ctx[((size_t)bh * S_ + i0 + r) * D_ + c4] = *(float4*)&stg[r * SGW + c4];
    }
}

// ---------------------------------------------------------------------------
// kernel_launch
// ---------------------------------------------------------------------------
extern "C" void kernel_launch(void* const* d_in, const int* in_sizes, int n_in,
                              void* d_out, int out_size)
{
    const float* Q    = (const float*)d_in[0];
    const float* K    = (const float*)d_in[1];
    const float* V    = (const float*)d_in[2];
    const int*   mask = (const int*)d_in[3];

    float* out  = (float*)d_out;
    float* ctx  = out;
    float* attn = out + (size_t)B_ * H_ * S_ * D_;

    static bool attrs_set = false;
    if (!attrs_set) {
        cudaFuncSetAttribute(scores_mma_kernel, cudaFuncAttributeMaxDynamicSharedMemorySize, SM_BYTES);
        cudaFuncSetAttribute(context_mma_kernel, cudaFuncAttributeMaxDynamicSharedMemorySize, SM_BYTES);
        attrs_set = true;
    }

    vt_kernel<<<dim3(S_ / 32, D_ / 32, B_ * H_), 256>>>(V);

    dim3 g1(S_ / 128, S_ / 128, B_ * H_);
    scores_mma_kernel<<<g1, 256, SM_BYTES>>>(Q, K, mask, attn);

    softmax_kernel<<<B_ * H_ * S_, 256>>>(attn);

    dim3 g3(S_ / 128, B_ * H_);
    context_mma_kernel<<<g3, 256, SM_BYTES>>>(attn, ctx);

    (void)in_sizes; (void)n_in; (void)out_size;
}

// round 10
// speedup vs baseline: 1.1981x; 1.1981x over previous
#include <cuda_runtime.h>
#include <cuda_bf16.h>
#include <cstdint>

#define B_ 2
#define H_ 16
#define S_ 2048
#define D_ 128
#define SCALE 0.08838834764831845f   // 1/sqrt(128)
#define NEG (-1e9f)

#define CW 72                        // chunk row stride (64 data + 8 pad) bf16
#define CH_ELEMS (128 * CW)          // elems per tile (single stage)
#define SM_BYTES (4 * CH_ELEMS * 2)  // 73728 B -> 2 CTAs/SM
#define SGW 132                      // fp32 staging row stride (floats)

// Pre-transposed V: Vt[bh][n][k] = V[bh][k][n], split into bf16 hi/lo
__device__ __align__(16) __nv_bfloat16 g_VtHi[(size_t)32 * 128 * 2048];
__device__ __align__(16) __nv_bfloat16 g_VtLo[(size_t)32 * 128 * 2048];

// ---------------------------------------------------------------------------
__device__ __forceinline__ void mma_bf16(float* d,
                                         uint32_t a0, uint32_t a1, uint32_t a2, uint32_t a3,
                                         uint32_t b0, uint32_t b1) {
    asm volatile(
        "mma.sync.aligned.m16n8k16.row.col.f32.bf16.bf16.f32 "
        "{%0,%1,%2,%3}, {%4,%5,%6,%7}, {%8,%9}, {%0,%1,%2,%3};"
        : "+f"(d[0]), "+f"(d[1]), "+f"(d[2]), "+f"(d[3])
        : "r"(a0), "r"(a1), "r"(a2), "r"(a3), "r"(b0), "r"(b1));
}

__device__ __forceinline__ void ldm_x4(uint32_t& r0, uint32_t& r1, uint32_t& r2, uint32_t& r3,
                                       uint32_t addr) {
    asm volatile("ldmatrix.sync.aligned.m8n8.x4.shared.b16 {%0,%1,%2,%3}, [%4];"
                 : "=r"(r0), "=r"(r1), "=r"(r2), "=r"(r3) : "r"(addr));
}

__device__ __forceinline__ uint32_t smem_u32(const void* p) {
    return (uint32_t)__cvta_generic_to_shared(p);
}

__device__ __forceinline__ uint32_t pack2(__nv_bfloat16 a, __nv_bfloat16 b) {
    return (uint32_t)__bfloat16_as_ushort(a) | ((uint32_t)__bfloat16_as_ushort(b) << 16);
}

__device__ __forceinline__ void store_hilo4(__nv_bfloat16* hi, __nv_bfloat16* lo,
                                            uint32_t off, float4 v) {
    __nv_bfloat16 h0 = __float2bfloat16(v.x), h1 = __float2bfloat16(v.y);
    __nv_bfloat16 h2 = __float2bfloat16(v.z), h3 = __float2bfloat16(v.w);
    __nv_bfloat16 l0 = __float2bfloat16(v.x - __bfloat162float(h0));
    __nv_bfloat16 l1 = __float2bfloat16(v.y - __bfloat162float(h1));
    __nv_bfloat16 l2 = __float2bfloat16(v.z - __bfloat162float(h2));
    __nv_bfloat16 l3 = __float2bfloat16(v.w - __bfloat162float(h3));
    uint2 hp; hp.x = pack2(h0, h1); hp.y = pack2(h2, h3);
    uint2 lp; lp.x = pack2(l0, l1); lp.y = pack2(l2, l3);
    *(uint2*)(hi + off) = hp;
    *(uint2*)(lo + off) = lp;
}

__device__ __forceinline__ float warpRedMax(float v) {
    #pragma unroll
    for (int o = 16; o > 0; o >>= 1) v = fmaxf(v, __shfl_xor_sync(0xffffffffu, v, o));
    return v;
}
__device__ __forceinline__ float warpRedSum(float v) {
    #pragma unroll
    for (int o = 16; o > 0; o >>= 1) v += __shfl_xor_sync(0xffffffffu, v, o);
    return v;
}

// MMA over one 64-wide chunk (4 ksteps), accumulators 16x4 per thread
__device__ __forceinline__ void mma_chunk(float acc[16][4],
                                          uint32_t aHi, uint32_t aLo,
                                          uint32_t bHi, uint32_t bLo) {
    #pragma unroll
    for (int ks = 0; ks < 4; ++ks) {
        const uint32_t kb = ks * 32;   // 16 bf16 = 32 bytes
        uint32_t ah0, ah1, ah2, ah3, al0, al1, al2, al3;
        ldm_x4(ah0, ah1, ah2, ah3, aHi + kb);
        ldm_x4(al0, al1, al2, al3, aLo + kb);
        #pragma unroll
        for (int nt = 0; nt < 16; nt += 2) {
            const uint32_t bo = nt * (8 * CW * 2) + kb;
            uint32_t bh0, bh1, bh2, bh3, bl0, bl1, bl2, bl3;
            ldm_x4(bh0, bh1, bh2, bh3, bHi + bo);
            ldm_x4(bl0, bl1, bl2, bl3, bLo + bo);
            mma_bf16(acc[nt],     ah0, ah1, ah2, ah3, bh0, bh1);
            mma_bf16(acc[nt],     ah0, ah1, ah2, ah3, bl0, bl1);
            mma_bf16(acc[nt],     al0, al1, al2, al3, bh0, bh1);
            mma_bf16(acc[nt + 1], ah0, ah1, ah2, ah3, bh2, bh3);
            mma_bf16(acc[nt + 1], ah0, ah1, ah2, ah3, bl2, bl3);
            mma_bf16(acc[nt + 1], al0, al1, al2, al3, bh2, bh3);
        }
    }
}

// ---------------------------------------------------------------------------
// K0: V -> Vt (transposed) bf16 hi/lo
// ---------------------------------------------------------------------------
__global__ __launch_bounds__(256) void vt_kernel(const float* __restrict__ V) {
    __shared__ float t[32][33];
    const int k0 = blockIdx.x * 32, n0 = blockIdx.y * 32, bh = blockIdx.z;
    const int tid = threadIdx.x, c = tid & 31, r0 = tid >> 5;
    const float* Vb = V + (size_t)bh * S_ * D_;
    #pragma unroll
    for (int rr = r0; rr < 32; rr += 8)
        t[rr][c] = Vb[(size_t)(k0 + rr) * D_ + n0 + c];
    __syncthreads();
    __nv_bfloat16* Hb = g_VtHi + (size_t)bh * D_ * S_;
    __nv_bfloat16* Lb = g_VtLo + (size_t)bh * D_ * S_;
    #pragma unroll
    for (int rr = r0; rr < 32; rr += 8) {
        float x = t[c][rr];
        __nv_bfloat16 h = __float2bfloat16(x);
        __nv_bfloat16 l = __float2bfloat16(x - __bfloat162float(h));
        size_t o = (size_t)(n0 + rr) * S_ + k0 + c;
        Hb[o] = h;
        Lb[o] = l;
    }
}

// ---------------------------------------------------------------------------
// K1: scores = Q K^T * scale + mask -> attn scratch. 128x128 tile per CTA.
// Single-buffered 64-wide k-chunks; 73.7KB smem -> 2 CTAs/SM.
// ---------------------------------------------------------------------------
__global__ __launch_bounds__(256, 2) void scores_mma_kernel(
    const float* __restrict__ Q, const float* __restrict__ K,
    const int* __restrict__ mask, float* __restrict__ attn)
{
    const int bh = blockIdx.z, b = bh >> 4;
    const int i0 = blockIdx.y * 128, j0 = blockIdx.x * 128;
    const int tid = threadIdx.x;

    if (j0 + 128 <= (i0 * 4) / 5) return;   // fully-window tile: no work

    float* attnBase = attn + ((size_t)bh * S_ + i0) * S_ + j0;

    extern __shared__ __nv_bfloat16 sm[];
    __nv_bfloat16* Ahi = sm;
    __nv_bfloat16* Alo = sm + CH_ELEMS;
    __nv_bfloat16* Bhi = sm + 2 * CH_ELEMS;
    __nv_bfloat16* Blo = sm + 3 * CH_ELEMS;

    const float* Qb = Q + ((size_t)bh * S_ + i0) * D_;
    const float* Kb = K + ((size_t)bh * S_ + j0) * D_;

    const int lane = tid & 31, warp = tid >> 5;
    const int g = lane >> 2, c = lane & 3;
    const int m0 = warp * 16;

    float acc[16][4];
    #pragma unroll
    for (int nt = 0; nt < 16; ++nt)
        #pragma unroll
        for (int q = 0; q < 4; ++q) acc[nt][q] = 0.0f;

    const uint32_t aRowOff = ((m0 + (lane & 15)) * CW + (lane >> 4) * 8) * 2;
    const uint32_t bRowOff = ((((lane >> 4) << 3) + (lane & 7)) * CW + ((lane >> 3) & 1) * 8) * 2;
    const uint32_t aHiA = smem_u32(Ahi) + aRowOff;
    const uint32_t aLoA = smem_u32(Alo) + aRowOff;
    const uint32_t bHiA = smem_u32(Bhi) + bRowOff;
    const uint32_t bLoA = smem_u32(Blo) + bRowOff;

    #pragma unroll
    for (int ch = 0; ch < 2; ++ch) {
        if (ch) __syncthreads();            // previous MMA done reading
        const int kc = ch * 64;
        #pragma unroll
        for (int it = 0; it < 8; ++it) {
            int idx = it * 256 + tid;
            int row = idx >> 4, c4 = (idx & 15) << 2;
            store_hilo4(Ahi, Alo, row * CW + c4, *(const float4*)&Qb[(size_t)row * D_ + kc + c4]);
            store_hilo4(Bhi, Blo, row * CW + c4, *(const float4*)&Kb[(size_t)row * D_ + kc + c4]);
        }
        __syncthreads();
        mma_chunk(acc, aHiA, aLoA, bHiA, bLoA);
    }
    __syncthreads();   // all warps done reading smem; reuse as fp32 staging

    float* stg = (float*)sm;
    #pragma unroll
    for (int nt = 0; nt < 16; ++nt) {
        *(float2*)&stg[(m0 + g) * SGW + nt * 8 + 2 * c]     = make_float2(acc[nt][0], acc[nt][1]);
        *(float2*)&stg[(m0 + g + 8) * SGW + nt * 8 + 2 * c] = make_float2(acc[nt][2], acc[nt][3]);
    }
    __syncthreads();

    const int* mB = mask + (size_t)b * S_ * S_;
    #pragma unroll
    for (int it = 0; it < 16; ++it) {
        int idx = it * 256 + tid;
        int r = idx >> 5, cc = (idx & 31) * 4;
        int i = i0 + r, thr = (i * 4) / 5, j = j0 + cc;
        int4 mv = *(const int4*)&mB[(size_t)i * S_ + j];
        float4 s = *(float4*)&stg[r * SGW + cc];
        float4 v;
        v.x = (mv.x || (j + 0) < thr) ? NEG : s.x * SCALE;
        v.y = (mv.y || (j + 1) < thr) ? NEG : s.y * SCALE;
        v.z = (mv.z || (j + 2) < thr) ? NEG : s.z * SCALE;
        v.w = (mv.w || (j + 3) < thr) ? NEG : s.w * SCALE;
        *(float4*)&attnBase[(size_t)r * S_ + cc] = v;
    }
}

// ---------------------------------------------------------------------------
// K2: row softmax. Reads only [jStart, S); zero-fills [0, jStart).
// ---------------------------------------------------------------------------
__global__ __launch_bounds__(256) void softmax_kernel(float* __restrict__ attn)
{
    const int row = blockIdx.x;
    const int i = row & (S_ - 1);
    const int i0 = i & ~127;
    const int jStart = (((i0 * 4) / 5) >> 7) << 7;
    float* p = attn + (size_t)row * S_;
    const int tid = threadIdx.x;

    const int n4 = (S_ - jStart) >> 2;
    float4* p4 = (float4*)(p + jStart);
    const bool val0 = tid < n4;
    const bool val1 = tid + 256 < n4;

    float4 v0 = make_float4(NEG, NEG, NEG, NEG);
    float4 v1 = make_float4(NEG, NEG, NEG, NEG);
    if (val0) v0 = p4[tid];
    if (val1) v1 = p4[tid + 256];

    __shared__ float red[8];

    float m = fmaxf(fmaxf(fmaxf(v0.x, v0.y), fmaxf(v0.z, v0.w)),
                    fmaxf(fmaxf(v1.x, v1.y), fmaxf(v1.z, v1.w)));
    m = warpRedMax(m);
    if ((tid & 31) == 0) red[tid >> 5] = m;
    __syncthreads();
    float bm = red[0];
    #pragma unroll
    for (int k = 1; k < 8; ++k) bm = fmaxf(bm, red[k]);
    __syncthreads();

    v0.x = __expf(v0.x - bm); v0.y = __expf(v0.y - bm);
    v0.z = __expf(v0.z - bm); v0.w = __expf(v0.w - bm);
    v1.x = __expf(v1.x - bm); v1.y = __expf(v1.y - bm);
    v1.z = __expf(v1.z - bm); v1.w = __expf(v1.w - bm);

    float s = 0.0f;
    if (val0) s += (v0.x + v0.y) + (v0.z + v0.w);
    if (val1) s += (v1.x + v1.y) + (v1.z + v1.w);
    s = warpRedSum(s);
    if ((tid & 31) == 0) red[tid >> 5] = s;
    __syncthreads();
    float bs = 0.0f;
    #pragma unroll
    for (int k = 0; k < 8; ++k) bs += red[k];

    const float inv = 1.0f / bs;
    if (val0) {
        v0.x *= inv; v0.y *= inv; v0.z *= inv; v0.w *= inv;
        p4[tid] = v0;
    }
    if (val1) {
        v1.x *= inv; v1.y *= inv; v1.z *= inv; v1.w *= inv;
        p4[tid + 256] = v1;
    }

    const float4 z = make_float4(0.f, 0.f, 0.f, 0.f);
    const int nz4 = jStart >> 2;
    for (int idx = tid; idx < nz4; idx += 256)
        ((float4*)p)[idx] = z;
}

// ---------------------------------------------------------------------------
// K3: context = attn @ V. 128x128 output per CTA.
// Single-buffered 64-wide k-chunks; 73.7KB smem -> 2 CTAs/SM.
// ---------------------------------------------------------------------------
__global__ __launch_bounds__(256, 2) void context_mma_kernel(
    const float* __restrict__ attn, float* __restrict__ ctx)
{
    const int i0 = blockIdx.x * 128, bh = blockIdx.y;
    const int tid = threadIdx.x;

    extern __shared__ __nv_bfloat16 sm[];
    __nv_bfloat16* Phi = sm;
    __nv_bfloat16* Plo = sm + CH_ELEMS;
    __nv_bfloat16* Vhi = sm + 2 * CH_ELEMS;
    __nv_bfloat16* Vlo = sm + 3 * CH_ELEMS;

    const float* Pb = attn + ((size_t)bh * S_ + i0) * S_;
    const __nv_bfloat16* VtH = g_VtHi + (size_t)bh * D_ * S_;
    const __nv_bfloat16* VtL = g_VtLo + (size_t)bh * D_ * S_;

    const int lane = tid & 31, warp = tid >> 5;
    const int g = lane >> 2, c = lane & 3;
    const int m0 = warp * 16;

    float acc[16][4];
    #pragma unroll
    for (int nt = 0; nt < 16; ++nt)
        #pragma unroll
        for (int q = 0; q < 4; ++q) acc[nt][q] = 0.0f;

    const uint32_t aRowOff = ((m0 + (lane & 15)) * CW + (lane >> 4) * 8) * 2;
    const uint32_t bRowOff = ((((lane >> 4) << 3) + (lane & 7)) * CW + ((lane >> 3) & 1) * 8) * 2;
    const uint32_t aHiA = smem_u32(Phi) + aRowOff;
    const uint32_t aLoA = smem_u32(Plo) + aRowOff;
    const uint32_t bHiA = smem_u32(Vhi) + bRowOff;
    const uint32_t bLoA = smem_u32(Vlo) + bRowOff;

    const int ch0 = (((i0 * 4) / 5) >> 7) * 2;   // first nonzero 64-chunk

    for (int ch = ch0; ch < 32; ++ch) {
        if (ch > ch0) __syncthreads();          // previous MMA done reading
        const int k0g = ch * 64;
        #pragma unroll
        for (int it = 0; it < 8; ++it) {
            int idx = it * 256 + tid;
            int row = idx >> 4, c4 = (idx & 15) << 2;
            store_hilo4(Phi, Plo, row * CW + c4,
                        *(const float4*)&Pb[(size_t)row * S_ + k0g + c4]);
        }
        #pragma unroll
        for (int it = 0; it < 4; ++it) {
            int idx = it * 256 + tid;
            int n = idx >> 3, k8 = (idx & 7) << 3;
            *(uint4*)(Vhi + n * CW + k8) = *(const uint4*)&VtH[(size_t)n * S_ + k0g + k8];
            *(uint4*)(Vlo + n * CW + k8) = *(const uint4*)&VtL[(size_t)n * S_ + k0g + k8];
        }
        __syncthreads();
        mma_chunk(acc, aHiA, aLoA, bHiA, bLoA);
    }
    __syncthreads();   // all warps done with smem; reuse as staging

    float* stg = (float*)sm;
    #pragma unroll
    for (int nt = 0; nt < 16; ++nt) {
        *(float2*)&stg[(m0 + g) * SGW + nt * 8 + 2 * c]     = make_float2(acc[nt][0], acc[nt][1]);
        *(float2*)&stg[(m0 + g + 8) * SGW + nt * 8 + 2 * c] = make_float2(acc[nt][2], acc[nt][3]);
    }
    __syncthreads();

    #pragma unroll
    for (int it = 0; it < 16; ++it) {
        int idx = it * 256 + tid;
        int r = idx >> 5, c4 = (idx & 31) << 2;
        *(float4*)&ctx[((size_t)bh * S_ + i0 + r) * D_ + c4] = *(float4*)&stg[r * SGW + c4];
    }
}

// ---------------------------------------------------------------------------
// kernel_launch
// ---------------------------------------------------------------------------
extern "C" void kernel_launch(void* const* d_in, const int* in_sizes, int n_in,
                              void* d_out, int out_size)
{
    const float* Q    = (const float*)d_in[0];
    const float* K    = (const float*)d_in[1];
    const float* V    = (const float*)d_in[2];
    const int*   mask = (const int*)d_in[3];

    float* out  = (float*)d_out;
    float* ctx  = out;
    float* attn = out + (size_t)B_ * H_ * S_ * D_;

    static bool attrs_set = false;
    if (!attrs_set) {
        cudaFuncSetAttribute(scores_mma_kernel, cudaFuncAttributeMaxDynamicSharedMemorySize, SM_BYTES);
        cudaFuncSetAttribute(context_mma_kernel, cudaFuncAttributeMaxDynamicSharedMemorySize, SM_BYTES);
        attrs_set = true;
    }

    vt_kernel<<<dim3(S_ / 32, D_ / 32, B_ * H_), 256>>>(V);

    dim3 g1(S_ / 128, S_ / 128, B_ * H_);
    scores_mma_kernel<<<g1, 256, SM_BYTES>>>(Q, K, mask, attn);

    softmax_kernel<<<B_ * H_ * S_, 256>>>(attn);

    dim3 g3(S_ / 128, B_ * H_);
    context_mma_kernel<<<g3, 256, SM_BYTES>>>(attn, ctx);

    (void)in_sizes; (void)n_in; (void)out_size;
}

// round 11
// speedup vs baseline: 1.2160x; 1.0150x over previous
#include <cuda_runtime.h>
#include <cuda_bf16.h>
#include <cstdint>

#define B_ 2
#define H_ 16
#define S_ 2048
#define D_ 128
#define SCALE 0.08838834764831845f   // 1/sqrt(128)
#define NEG (-1e9f)

#define CW 72                        // chunk row stride (64 data + 8 pad) bf16
#define CH_ELEMS (128 * CW)          // elems per tile (single stage)
#define SM_BYTES_S (4 * CH_ELEMS * 2)   // scores: 73728 B  -> 2 CTAs/SM
#define SM_BYTES_C (6 * CH_ELEMS * 2)   // ctx: P hi/lo + V hi/lo x2 = 110592 B -> 2 CTAs/SM
#define SGW 132                      // fp32 staging row stride (floats)

// Pre-transposed V: Vt[bh][n][k] = V[bh][k][n], split into bf16 hi/lo
__device__ __align__(16) __nv_bfloat16 g_VtHi[(size_t)32 * 128 * 2048];
__device__ __align__(16) __nv_bfloat16 g_VtLo[(size_t)32 * 128 * 2048];

// ---------------------------------------------------------------------------
__device__ __forceinline__ void mma_bf16(float* d,
                                         uint32_t a0, uint32_t a1, uint32_t a2, uint32_t a3,
                                         uint32_t b0, uint32_t b1) {
    asm volatile(
        "mma.sync.aligned.m16n8k16.row.col.f32.bf16.bf16.f32 "
        "{%0,%1,%2,%3}, {%4,%5,%6,%7}, {%8,%9}, {%0,%1,%2,%3};"
        : "+f"(d[0]), "+f"(d[1]), "+f"(d[2]), "+f"(d[3])
        : "r"(a0), "r"(a1), "r"(a2), "r"(a3), "r"(b0), "r"(b1));
}

__device__ __forceinline__ void ldm_x4(uint32_t& r0, uint32_t& r1, uint32_t& r2, uint32_t& r3,
                                       uint32_t addr) {
    asm volatile("ldmatrix.sync.aligned.m8n8.x4.shared.b16 {%0,%1,%2,%3}, [%4];"
                 : "=r"(r0), "=r"(r1), "=r"(r2), "=r"(r3) : "r"(addr));
}

__device__ __forceinline__ uint32_t smem_u32(const void* p) {
    return (uint32_t)__cvta_generic_to_shared(p);
}

__device__ __forceinline__ void cp_async16(uint32_t dst, const void* src) {
    asm volatile("cp.async.cg.shared.global [%0], [%1], 16;" :: "r"(dst), "l"(src));
}
#define CP_COMMIT() asm volatile("cp.async.commit_group;" ::: "memory")
#define CP_WAIT(n)  asm volatile("cp.async.wait_group %0;" :: "n"(n) : "memory")

__device__ __forceinline__ uint32_t pack2(__nv_bfloat16 a, __nv_bfloat16 b) {
    return (uint32_t)__bfloat16_as_ushort(a) | ((uint32_t)__bfloat16_as_ushort(b) << 16);
}

__device__ __forceinline__ void store_hilo4(__nv_bfloat16* hi, __nv_bfloat16* lo,
                                            uint32_t off, float4 v) {
    __nv_bfloat16 h0 = __float2bfloat16(v.x), h1 = __float2bfloat16(v.y);
    __nv_bfloat16 h2 = __float2bfloat16(v.z), h3 = __float2bfloat16(v.w);
    __nv_bfloat16 l0 = __float2bfloat16(v.x - __bfloat162float(h0));
    __nv_bfloat16 l1 = __float2bfloat16(v.y - __bfloat162float(h1));
    __nv_bfloat16 l2 = __float2bfloat16(v.z - __bfloat162float(h2));
    __nv_bfloat16 l3 = __float2bfloat16(v.w - __bfloat162float(h3));
    uint2 hp; hp.x = pack2(h0, h1); hp.y = pack2(h2, h3);
    uint2 lp; lp.x = pack2(l0, l1); lp.y = pack2(l2, l3);
    *(uint2*)(hi + off) = hp;
    *(uint2*)(lo + off) = lp;
}

__device__ __forceinline__ float warpRedMax(float v) {
    #pragma unroll
    for (int o = 16; o > 0; o >>= 1) v = fmaxf(v, __shfl_xor_sync(0xffffffffu, v, o));
    return v;
}
__device__ __forceinline__ float warpRedSum(float v) {
    #pragma unroll
    for (int o = 16; o > 0; o >>= 1) v += __shfl_xor_sync(0xffffffffu, v, o);
    return v;
}

// MMA over one 64-wide chunk (4 ksteps), accumulators 16x4 per thread
__device__ __forceinline__ void mma_chunk(float acc[16][4],
                                          uint32_t aHi, uint32_t aLo,
                                          uint32_t bHi, uint32_t bLo) {
    #pragma unroll
    for (int ks = 0; ks < 4; ++ks) {
        const uint32_t kb = ks * 32;   // 16 bf16 = 32 bytes
        uint32_t ah0, ah1, ah2, ah3, al0, al1, al2, al3;
        ldm_x4(ah0, ah1, ah2, ah3, aHi + kb);
        ldm_x4(al0, al1, al2, al3, aLo + kb);
        #pragma unroll
        for (int nt = 0; nt < 16; nt += 2) {
            const uint32_t bo = nt * (8 * CW * 2) + kb;
            uint32_t bh0, bh1, bh2, bh3, bl0, bl1, bl2, bl3;
            ldm_x4(bh0, bh1, bh2, bh3, bHi + bo);
            ldm_x4(bl0, bl1, bl2, bl3, bLo + bo);
            mma_bf16(acc[nt],     ah0, ah1, ah2, ah3, bh0, bh1);
            mma_bf16(acc[nt],     ah0, ah1, ah2, ah3, bl0, bl1);
            mma_bf16(acc[nt],     al0, al1, al2, al3, bh0, bh1);
            mma_bf16(acc[nt + 1], ah0, ah1, ah2, ah3, bh2, bh3);
            mma_bf16(acc[nt + 1], ah0, ah1, ah2, ah3, bl2, bl3);
            mma_bf16(acc[nt + 1], al0, al1, al2, al3, bh2, bh3);
        }
    }
}

// ---------------------------------------------------------------------------
// K0: V -> Vt (transposed) bf16 hi/lo
// ---------------------------------------------------------------------------
__global__ __launch_bounds__(256) void vt_kernel(const float* __restrict__ V) {
    __shared__ float t[32][33];
    const int k0 = blockIdx.x * 32, n0 = blockIdx.y * 32, bh = blockIdx.z;
    const int tid = threadIdx.x, c = tid & 31, r0 = tid >> 5;
    const float* Vb = V + (size_t)bh * S_ * D_;
    #pragma unroll
    for (int rr = r0; rr < 32; rr += 8)
        t[rr][c] = Vb[(size_t)(k0 + rr) * D_ + n0 + c];
    __syncthreads();
    __nv_bfloat16* Hb = g_VtHi + (size_t)bh * D_ * S_;
    __nv_bfloat16* Lb = g_VtLo + (size_t)bh * D_ * S_;
    #pragma unroll
    for (int rr = r0; rr < 32; rr += 8) {
        float x = t[c][rr];
        __nv_bfloat16 h = __float2bfloat16(x);
        __nv_bfloat16 l = __float2bfloat16(x - __bfloat162float(h));
        size_t o = (size_t)(n0 + rr) * S_ + k0 + c;
        Hb[o] = h;
        Lb[o] = l;
    }
}

// ---------------------------------------------------------------------------
// K1: scores = Q K^T * scale + mask -> attn scratch. 128x128 tile per CTA.
// Window CTAs write the FINAL attn zeros for their tile (softmax skips them).
// ---------------------------------------------------------------------------
__global__ __launch_bounds__(256, 2) void scores_mma_kernel(
    const float* __restrict__ Q, const float* __restrict__ K,
    const int* __restrict__ mask, float* __restrict__ attn)
{
    const int bh = blockIdx.z, b = bh >> 4;
    const int i0 = blockIdx.y * 128, j0 = blockIdx.x * 128;
    const int tid = threadIdx.x;

    float* attnBase = attn + ((size_t)bh * S_ + i0) * S_ + j0;

    if (j0 + 128 <= (i0 * 4) / 5) {
        // fully-window tile: final attn here is exactly 0 — write it now
        const float4 z = make_float4(0.f, 0.f, 0.f, 0.f);
        #pragma unroll
        for (int it = 0; it < 16; ++it) {
            int idx = it * 256 + tid;
            *(float4*)&attnBase[(size_t)(idx >> 5) * S_ + ((idx & 31) << 2)] = z;
        }
        return;
    }

    extern __shared__ __nv_bfloat16 sm[];
    __nv_bfloat16* Ahi = sm;
    __nv_bfloat16* Alo = sm + CH_ELEMS;
    __nv_bfloat16* Bhi = sm + 2 * CH_ELEMS;
    __nv_bfloat16* Blo = sm + 3 * CH_ELEMS;

    const float* Qb = Q + ((size_t)bh * S_ + i0) * D_;
    const float* Kb = K + ((size_t)bh * S_ + j0) * D_;

    const int lane = tid & 31, warp = tid >> 5;
    const int g = lane >> 2, c = lane & 3;
    const int m0 = warp * 16;

    float acc[16][4];
    #pragma unroll
    for (int nt = 0; nt < 16; ++nt)
        #pragma unroll
        for (int q = 0; q < 4; ++q) acc[nt][q] = 0.0f;

    const uint32_t aRowOff = ((m0 + (lane & 15)) * CW + (lane >> 4) * 8) * 2;
    const uint32_t bRowOff = ((((lane >> 4) << 3) + (lane & 7)) * CW + ((lane >> 3) & 1) * 8) * 2;
    const uint32_t aHiA = smem_u32(Ahi) + aRowOff;
    const uint32_t aLoA = smem_u32(Alo) + aRowOff;
    const uint32_t bHiA = smem_u32(Bhi) + bRowOff;
    const uint32_t bLoA = smem_u32(Blo) + bRowOff;

    #pragma unroll
    for (int ch = 0; ch < 2; ++ch) {
        if (ch) __syncthreads();            // previous MMA done reading
        const int kc = ch * 64;
        #pragma unroll
        for (int it = 0; it < 8; ++it) {
            int idx = it * 256 + tid;
            int row = idx >> 4, c4 = (idx & 15) << 2;
            store_hilo4(Ahi, Alo, row * CW + c4, *(const float4*)&Qb[(size_t)row * D_ + kc + c4]);
            store_hilo4(Bhi, Blo, row * CW + c4, *(const float4*)&Kb[(size_t)row * D_ + kc + c4]);
        }
        __syncthreads();
        mma_chunk(acc, aHiA, aLoA, bHiA, bLoA);
    }
    __syncthreads();   // all warps done reading smem; reuse as fp32 staging

    float* stg = (float*)sm;
    #pragma unroll
    for (int nt = 0; nt < 16; ++nt) {
        *(float2*)&stg[(m0 + g) * SGW + nt * 8 + 2 * c]     = make_float2(acc[nt][0], acc[nt][1]);
        *(float2*)&stg[(m0 + g + 8) * SGW + nt * 8 + 2 * c] = make_float2(acc[nt][2], acc[nt][3]);
    }
    __syncthreads();

    const int* mB = mask + (size_t)b * S_ * S_;
    #pragma unroll
    for (int it = 0; it < 16; ++it) {
        int idx = it * 256 + tid;
        int r = idx >> 5, cc = (idx & 31) * 4;
        int i = i0 + r, thr = (i * 4) / 5, j = j0 + cc;
        int4 mv = *(const int4*)&mB[(size_t)i * S_ + j];
        float4 s = *(float4*)&stg[r * SGW + cc];
        float4 v;
        v.x = (mv.x || (j + 0) < thr) ? NEG : s.x * SCALE;
        v.y = (mv.y || (j + 1) < thr) ? NEG : s.y * SCALE;
        v.z = (mv.z || (j + 2) < thr) ? NEG : s.z * SCALE;
        v.w = (mv.w || (j + 3) < thr) ? NEG : s.w * SCALE;
        *(float4*)&attnBase[(size_t)r * S_ + cc] = v;
    }
}

// ---------------------------------------------------------------------------
// K2: row softmax over [jStart, S) only. The [0, jStart) region already holds
// final zeros (written by the scores kernel's window CTAs).
// ---------------------------------------------------------------------------
__global__ __launch_bounds__(256) void softmax_kernel(float* __restrict__ attn)
{
    const int row = blockIdx.x;
    const int i = row & (S_ - 1);
    const int i0 = i & ~127;
    const int jStart = (((i0 * 4) / 5) >> 7) << 7;
    float* p = attn + (size_t)row * S_;
    const int tid = threadIdx.x;

    const int n4 = (S_ - jStart) >> 2;
    float4* p4 = (float4*)(p + jStart);
    const bool val0 = tid < n4;
    const bool val1 = tid + 256 < n4;

    float4 v0 = make_float4(NEG, NEG, NEG, NEG);
    float4 v1 = make_float4(NEG, NEG, NEG, NEG);
    if (val0) v0 = p4[tid];
    if (val1) v1 = p4[tid + 256];

    __shared__ float red[8];

    float m = fmaxf(fmaxf(fmaxf(v0.x, v0.y), fmaxf(v0.z, v0.w)),
                    fmaxf(fmaxf(v1.x, v1.y), fmaxf(v1.z, v1.w)));
    m = warpRedMax(m);
    if ((tid & 31) == 0) red[tid >> 5] = m;
    __syncthreads();
    float bm = red[0];
    #pragma unroll
    for (int k = 1; k < 8; ++k) bm = fmaxf(bm, red[k]);
    __syncthreads();

    v0.x = __expf(v0.x - bm); v0.y = __expf(v0.y - bm);
    v0.z = __expf(v0.z - bm); v0.w = __expf(v0.w - bm);
    v1.x = __expf(v1.x - bm); v1.y = __expf(v1.y - bm);
    v1.z = __expf(v1.z - bm); v1.w = __expf(v1.w - bm);

    float s = 0.0f;
    if (val0) s += (v0.x + v0.y) + (v0.z + v0.w);
    if (val1) s += (v1.x + v1.y) + (v1.z + v1.w);
    s = warpRedSum(s);
    if ((tid & 31) == 0) red[tid >> 5] = s;
    __syncthreads();
    float bs = 0.0f;
    #pragma unroll
    for (int k = 0; k < 8; ++k) bs += red[k];

    const float inv = 1.0f / bs;
    if (val0) {
        v0.x *= inv; v0.y *= inv; v0.z *= inv; v0.w *= inv;
        p4[tid] = v0;
    }
    if (val1) {
        v1.x *= inv; v1.y *= inv; v1.z *= inv; v1.w *= inv;
        p4[tid + 256] = v1;
    }
}

// ---------------------------------------------------------------------------
// K3: context = attn @ V. 128x128 output per CTA.
// P single-buffered (fp32->hi/lo convert); V double-buffered via cp.async
// (issued one chunk ahead, zero register cost).
// ---------------------------------------------------------------------------
__global__ __launch_bounds__(256, 2) void context_mma_kernel(
    const float* __restrict__ attn, float* __restrict__ ctx)
{
    const int i0 = blockIdx.x * 128, bh = blockIdx.y;
    const int tid = threadIdx.x;

    extern __shared__ __nv_bfloat16 sm[];
    __nv_bfloat16* Phi = sm;
    __nv_bfloat16* Plo = sm + CH_ELEMS;
    // V stages: [2CH,3CH) = hi0, [3CH,4CH) = lo0, [4CH,5CH) = hi1, [5CH,6CH) = lo1
    __nv_bfloat16* Vst = sm + 2 * CH_ELEMS;

    const float* Pb = attn + ((size_t)bh * S_ + i0) * S_;
    const __nv_bfloat16* VtH = g_VtHi + (size_t)bh * D_ * S_;
    const __nv_bfloat16* VtL = g_VtLo + (size_t)bh * D_ * S_;

    const int lane = tid & 31, warp = tid >> 5;
    const int g = lane >> 2, c = lane & 3;
    const int m0 = warp * 16;

    float acc[16][4];
    #pragma unroll
    for (int nt = 0; nt < 16; ++nt)
        #pragma unroll
        for (int q = 0; q < 4; ++q) acc[nt][q] = 0.0f;

    const uint32_t aRowOff = ((m0 + (lane & 15)) * CW + (lane >> 4) * 8) * 2;
    const uint32_t bRowOff = ((((lane >> 4) << 3) + (lane & 7)) * CW + ((lane >> 3) & 1) * 8) * 2;
    const uint32_t aHiA = smem_u32(Phi) + aRowOff;
    const uint32_t aLoA = smem_u32(Plo) + aRowOff;
    const uint32_t vBase = smem_u32(Vst);
    // stage s: hi at vBase + s*2*CH*2, lo at hi + CH*2
    const uint32_t bHiA0 = vBase + bRowOff;
    const uint32_t bLoA0 = vBase + CH_ELEMS * 2 + bRowOff;

    // per-thread cp.async source/dest offsets for V (4 uint4 per array)
    const int vn = tid >> 3, vk8 = (tid & 7) << 3;   // n row, k offset within chunk

    const int ch0 = (((i0 * 4) / 5) >> 7) * 2;   // first nonzero 64-chunk

    // prologue: issue V(ch0) into stage ch0&1
    {
        const int k0g = ch0 * 64;
        const uint32_t st = (uint32_t)(ch0 & 1) * (2 * CH_ELEMS * 2);
        #pragma unroll
        for (int it = 0; it < 4; ++it) {
            int n = vn + it * 32;
            uint32_t doff = (n * CW + vk8) * 2;
            cp_async16(vBase + st + doff, &VtH[(size_t)n * S_ + k0g + vk8]);
            cp_async16(vBase + st + CH_ELEMS * 2 + doff, &VtL[(size_t)n * S_ + k0g + vk8]);
        }
        CP_COMMIT();
    }

    for (int ch = ch0; ch < 32; ++ch) {
        if (ch > ch0) __syncthreads();          // previous MMA done reading P
        const int k0g = ch * 64;
        // P: fp32 -> hi/lo into single buffer
        #pragma unroll
        for (int it = 0; it < 8; ++it) {
            int idx = it * 256 + tid;
            int row = idx >> 4, c4 = (idx & 15) << 2;
            store_hilo4(Phi, Plo, row * CW + c4,
                        *(const float4*)&Pb[(size_t)row * S_ + k0g + c4]);
        }
        // issue V(ch+1) into the other stage
        if (ch + 1 < 32) {
            const int k1g = (ch + 1) * 64;
            const uint32_t st = (uint32_t)((ch + 1) & 1) * (2 * CH_ELEMS * 2);
            #pragma unroll
            for (int it = 0; it < 4; ++it) {
                int n = vn + it * 32;
                uint32_t doff = (n * CW + vk8) * 2;
                cp_async16(vBase + st + doff, &VtH[(size_t)n * S_ + k1g + vk8]);
                cp_async16(vBase + st + CH_ELEMS * 2 + doff, &VtL[(size_t)n * S_ + k1g + vk8]);
            }
            CP_COMMIT();
            CP_WAIT(1);    // V(ch) complete; V(ch+1) may remain in flight
        } else {
            CP_WAIT(0);
        }
        __syncthreads();
        const uint32_t st = (uint32_t)(ch & 1) * (2 * CH_ELEMS * 2);
        mma_chunk(acc, aHiA, aLoA, bHiA0 + st, bLoA0 + st);
    }
    __syncthreads();   // all warps done with smem; reuse as staging

    float* stg = (float*)sm;
    #pragma unroll
    for (int nt = 0; nt < 16; ++nt) {
        *(float2*)&stg[(m0 + g) * SGW + nt * 8 + 2 * c]     = make_float2(acc[nt][0], acc[nt][1]);
        *(float2*)&stg[(m0 + g + 8) * SGW + nt * 8 + 2 * c] = make_float2(acc[nt][2], acc[nt][3]);
    }
    __syncthreads();

    #pragma unroll
    for (int it = 0; it < 16; ++it) {
        int idx = it * 256 + tid;
        int r = idx >> 5, c4 = (idx & 31) << 2;
        *(float4*)&ctx[((size_t)bh * S_ + i0 + r) * D_ + c4] = *(float4*)&stg[r * SGW + c4];
    }
}

// ---------------------------------------------------------------------------
// kernel_launch
// ---------------------------------------------------------------------------
extern "C" void kernel_launch(void* const* d_in, const int* in_sizes, int n_in,
                              void* d_out, int out_size)
{
    const float* Q    = (const float*)d_in[0];
    const float* K    = (const float*)d_in[1];
    const float* V    = (const float*)d_in[2];
    const int*   mask = (const int*)d_in[3];

    float* out  = (float*)d_out;
    float* ctx  = out;
    float* attn = out + (size_t)B_ * H_ * S_ * D_;

    static bool attrs_set = false;
    if (!attrs_set) {
        cudaFuncSetAttribute(scores_mma_kernel, cudaFuncAttributeMaxDynamicSharedMemorySize, SM_BYTES_S);
        cudaFuncSetAttribute(context_mma_kernel, cudaFuncAttributeMaxDynamicSharedMemorySize, SM_BYTES_C);
        attrs_set = true;
    }

    vt_kernel<<<dim3(S_ / 32, D_ / 32, B_ * H_), 256>>>(V);

    dim3 g1(S_ / 128, S_ / 128, B_ * H_);
    scores_mma_kernel<<<g1, 256, SM_BYTES_S>>>(Q, K, mask, attn);

    softmax_kernel<<<B_ * H_ * S_, 256>>>(attn);

    dim3 g3(S_ / 128, B_ * H_);
    context_mma_kernel<<<g3, 256, SM_BYTES_C>>>(attn, ctx);

    (void)in_sizes; (void)n_in; (void)out_size;
}